// round 16
// baseline (speedup 1.0000x reference)
#include <cuda_runtime.h>
#include <cuda_fp16.h>
#include <math.h>
#include <stdint.h>

#define NTOK 65536
#define DH 256
#define DF 1024
#define NB 4
#define TM 64
#define THREADS 512

#define XS_STRIDE 144   // u32 units; ≡16 (mod 32): conflict-free uint4 LDS phases
#define HS_STRIDE 80
#define HS_BUF (64 * HS_STRIDE)

// smem offsets in u32 units
#define OFF_TOK 0
#define OFF_RED 64                 // 64 rows x 8 warp-partials
#define OFF_XS 576
#define OFF_HS (OFF_XS + 64 * XS_STRIDE)
#define SMEM_U32 (OFF_HS + 2 * HS_BUF)

__device__ int g_counts[NB];
__device__ int g_idx[NB * NTOK];
// fp16 weights in m16n8k16 fragment-permuted layout.
// Each (fc, step, f/h) cell holds 32 fp16 = 4 uint4.
__device__ uint4 g_w1h[NB * 8 * 8 * 128 * 4];   // [br][fc8][step8][f128][4 uint4]
__device__ uint4 g_w2h[NB * 8 * 4 * 256 * 4];   // [br][fc8][step4][h256][4 uint4]

static __device__ __forceinline__ void mma16(float* c,
    uint32_t a0, uint32_t a1, uint32_t a2, uint32_t a3, uint32_t b0, uint32_t b1) {
    asm volatile("mma.sync.aligned.m16n8k16.row.col.f32.f16.f16.f32 "
                 "{%0,%1,%2,%3}, {%4,%5,%6,%7}, {%8,%9}, {%0,%1,%2,%3};"
                 : "+f"(c[0]), "+f"(c[1]), "+f"(c[2]), "+f"(c[3])
                 : "r"(a0), "r"(a1), "r"(a2), "r"(a3), "r"(b0), "r"(b1));
}

// fast ELU: abs error ~5e-7 near 0 (<< fp16 rounding of H)
static __device__ __forceinline__ float elu_fast(float v) {
    return v > 0.f ? v : (__expf(v) - 1.f);
}

// permutation within a 32-k block: element position for k
// t=(k&7)>>1, grp=(k>>4)&1, hi=(k>>3)&1, odd=k&1 -> p = t*8 + grp*4 + hi*2 + odd
static __device__ __forceinline__ int perm32(int kk) {
    return ((kk & 7) >> 1) * 8 + ((kk >> 4) & 1) * 4 + ((kk >> 3) & 1) * 2 + (kk & 1);
}

__global__ void reset_counts_kernel() {
    if (threadIdx.x < NB) g_counts[threadIdx.x] = 0;
}
__global__ void bucket_kernel(const int* __restrict__ b_seq) {
    int i = blockIdx.x * blockDim.x + threadIdx.x;
    int b = b_seq[i];
    if (b > 0) {
        int pos = atomicAdd(&g_counts[b - 1], 1);
        g_idx[(b - 1) * NTOK + pos] = i;
    }
}
__global__ void zero_kernel(const int* __restrict__ b_seq, float4* __restrict__ out) {
    int gid = blockIdx.x * blockDim.x + threadIdx.x;
    int tok = gid >> 6;
    if (b_seq[tok] == 0) out[gid] = make_float4(0.f, 0.f, 0.f, 0.f);
}

// merged weight prep: blocks [0,1024) do w1, [1024,2048) do w2 — overlaps the two
// latency-bound streams in one launch.
__global__ void prep_w_kernel(const float* __restrict__ w1, const float* __restrict__ w2) {
    int bid = blockIdx.x;
    if (bid < 1024) {
        int t = bid * blockDim.x + threadIdx.x;
        int e = t * 4;
        int br = e >> 18;
        int rem = e & 262143;
        int f = rem >> 8;
        int k = rem & 255;
        float4 v = *(const float4*)(w1 + e);
        int fc = f >> 7, fl = f & 127, step = k >> 5, kk = k & 31;   // kk % 4 == 0
        int p = perm32(kk);                                           // even
        __half2* dst = (__half2*)g_w1h + (((((br * 8 + fc) * 8 + step) * 128 + fl) * 32) + p) / 2;
        dst[0] = __floats2half2_rn(v.x, v.y);
        dst[4] = __floats2half2_rn(v.z, v.w);   // k+2,k+3 -> p+8
    } else {
        int t = (bid - 1024) * blockDim.x + threadIdx.x;
        int e = t * 4;
        int br = e >> 18;
        int rem = e & 262143;
        int h = rem >> 10;
        int f = rem & 1023;
        float4 v = *(const float4*)(w2 + e);
        int fc = f >> 7, fl = f & 127, step = fl >> 5, kk = fl & 31;  // kk % 4 == 0
        int p = perm32(kk);
        __half2* dst = (__half2*)g_w2h + (((((br * 8 + fc) * 4 + step) * 256 + h) * 32) + p) / 2;
        dst[0] = __floats2half2_rn(v.x, v.y);
        dst[4] = __floats2half2_rn(v.z, v.w);
    }
}

__global__ __launch_bounds__(THREADS, 1)
void ffn_mma_kernel(const float* __restrict__ x,
                    const float* __restrict__ b1, const float* __restrict__ b2,
                    const float* __restrict__ gamma, const float* __restrict__ beta,
                    float* __restrict__ out)
{
    const int br = blockIdx.y;
    const int count = g_counts[br];
    const int t0 = blockIdx.x * TM;
    if (t0 >= count) return;

    extern __shared__ uint32_t smem[];
    int* s_tok = (int*)(smem + OFF_TOK);
    float* red = (float*)(smem + OFF_RED);
    uint32_t* Xs = smem + OFF_XS;

    const int tid = threadIdx.x;
    const int wid = tid >> 5, lane = tid & 31;
    const int g = lane >> 2, tig = lane & 3;
    const int wm = wid & 1, wn = wid >> 1;   // 2 m-warps x 8 n-warps

    if (tid < TM) {
        int r = t0 + tid;
        s_tok[tid] = g_idx[br * NTOK + (r < count ? r : count - 1)];
    }
    __syncthreads();

    // ---- stage X tile (once), fp16 + k-permuted: 8 threads/row, one 32-k block each ----
    {
        int row = tid >> 3, q = tid & 7;
        const float4* src = (const float4*)(x + (size_t)s_tok[row] * DH) + q * 8;
        uint32_t* xr = Xs + row * XS_STRIDE + q * 16;
        #pragma unroll
        for (int j = 0; j < 8; j++) {
            float4 d = src[j];
            int p = perm32(j * 4);
            __half2 h01 = __floats2half2_rn(d.x, d.y);
            __half2 h23 = __floats2half2_rn(d.z, d.w);
            uint32_t* dst = xr + (p >> 1);
            dst[0] = *(uint32_t*)&h01;
            dst[4] = *(uint32_t*)&h23;
        }
    }

    // lane-constant uint4 stream bases into the permuted weight arrays.
    // B-fragment streams are LINEAR across fc:
    //   GEMM1: w1s + t1*512,  t1 = fc*8 + s,  t1 in [0,64)
    //   GEMM2: w2s + t2*1024, t2 = fc*4 + s,  t2 in [0,32)
    const int c1base = ((wn * 16 + g) << 2) + tig;
    const int c2base = ((wn * 32 + g) << 2) + tig;
    const uint4* w1s = g_w1h + (size_t)br * 8 * 4096 + c1base;
    const uint4* w2s = g_w2h + (size_t)br * 8 * 4096 + c2base;

    float acc2[2][4][4];
    #pragma unroll
    for (int a = 0; a < 2; a++)
        #pragma unroll
        for (int bq = 0; bq < 4; bq++)
            #pragma unroll
            for (int cq = 0; cq < 4; cq++) acc2[a][bq][cq] = 0.f;

    // seed GEMM1 4-slot ring with t1 = 0, 1 (prefetch distance 2).
    // slot index = t1 & 3 (static: fc*8 ≡ 0 mod 4).
    uint4 bb1[4][2];
    #pragma unroll
    for (int nt = 0; nt < 2; nt++) {
        bb1[0][nt] = __ldg(w1s + nt * 32);
        bb1[1][nt] = __ldg(w1s + 512 + nt * 32);
    }
    uint4 bb2[2][4];

    __syncthreads();

    #pragma unroll 1
    for (int fc = 0; fc < 8; fc++) {
        uint32_t* Hs = smem + OFF_HS + (fc & 1) * HS_BUF;

        // ========== GEMM1: C1[64x128] = X * W1chunk^T, 8 steps of k=32 ==========
        float c1[2][2][4];
        #pragma unroll
        for (int a = 0; a < 2; a++)
            #pragma unroll
            for (int bq = 0; bq < 2; bq++)
                #pragma unroll
                for (int cq = 0; cq < 4; cq++) c1[a][bq][cq] = 0.f;

        #pragma unroll
        for (int s = 0; s < 8; s++) {
            int t1 = fc * 8 + s;
            if (t1 + 2 < 64) {      // distance-2 cross-fc prefetch into slot (s+2)&3
                const uint4* p = w1s + (t1 + 2) * 512;
                #pragma unroll
                for (int nt = 0; nt < 2; nt++)
                    bb1[(s + 2) & 3][nt] = __ldg(p + nt * 32);
            }
            int cb = s * 16 + 4 * tig;
            uint4 aL[2], aH[2];
            #pragma unroll
            for (int mt = 0; mt < 2; mt++) {
                int r0 = wm * 32 + mt * 16 + g;
                aL[mt] = *(const uint4*)(Xs + r0 * XS_STRIDE + cb);
                aH[mt] = *(const uint4*)(Xs + (r0 + 8) * XS_STRIDE + cb);
            }
            #pragma unroll
            for (int mt = 0; mt < 2; mt++)
                #pragma unroll
                for (int nt = 0; nt < 2; nt++) {
                    const uint4 bf = bb1[s & 3][nt];
                    mma16(c1[mt][nt], aL[mt].x, aH[mt].x, aL[mt].y, aH[mt].y, bf.x, bf.y);
                    mma16(c1[mt][nt], aL[mt].z, aH[mt].z, aL[mt].w, aH[mt].w, bf.z, bf.w);
                }
        }

        // ========== bias + fast ELU -> Hs[fc&1] (fp16, permuted) ==========
        {
            const float* b1g = b1 + br * DF + fc * 128;
            #pragma unroll
            for (int nt = 0; nt < 2; nt++) {
                int col0 = wn * 16 + nt * 8 + 2 * tig;
                float ba = b1g[col0], bb = b1g[col0 + 1];
                int block = col0 >> 5;
                int p = perm32(col0 & 31);          // even
                int uoff = block * 16 + (p >> 1);
                #pragma unroll
                for (int mt = 0; mt < 2; mt++) {
                    int r0 = wm * 32 + mt * 16 + g;
                    float v00 = elu_fast(c1[mt][nt][0] + ba);
                    float v01 = elu_fast(c1[mt][nt][1] + bb);
                    float v10 = elu_fast(c1[mt][nt][2] + ba);
                    float v11 = elu_fast(c1[mt][nt][3] + bb);
                    __half2 hlo = __floats2half2_rn(v00, v01);
                    __half2 hhi = __floats2half2_rn(v10, v11);
                    Hs[r0 * HS_STRIDE + uoff] = *(uint32_t*)&hlo;
                    Hs[(r0 + 8) * HS_STRIDE + uoff] = *(uint32_t*)&hhi;
                }
            }
        }
        if (fc == 0) {    // seed GEMM2 ring before the barrier so the barrier hides L2
            #pragma unroll
            for (int nt = 0; nt < 4; nt++) bb2[0][nt] = __ldg(w2s + nt * 32);
        }
        __syncthreads();   // single barrier per fc: Hs[fc&1] writes -> reads.

        // ========== GEMM2: acc2[64x256] += H * W2chunk^T, 4 steps of k=32 ==========
        #pragma unroll
        for (int s = 0; s < 4; s++) {
            int t2 = fc * 4 + s;
            if (t2 + 1 < 32) {   // cross-fc prefetch: next fc's step0 lands during GEMM1+barrier
                const uint4* p = w2s + (t2 + 1) * 1024;
                #pragma unroll
                for (int nt = 0; nt < 4; nt++)
                    bb2[(s + 1) & 1][nt] = __ldg(p + nt * 32);
            }
            int cb = s * 16 + 4 * tig;
            uint4 aL[2], aH[2];
            #pragma unroll
            for (int mt = 0; mt < 2; mt++) {
                int r0 = wm * 32 + mt * 16 + g;
                aL[mt] = *(const uint4*)(Hs + r0 * HS_STRIDE + cb);
                aH[mt] = *(const uint4*)(Hs + (r0 + 8) * HS_STRIDE + cb);
            }
            #pragma unroll
            for (int nt = 0; nt < 4; nt++) {
                const uint4 bf = bb2[s & 1][nt];
                #pragma unroll
                for (int mt = 0; mt < 2; mt++) {
                    mma16(acc2[mt][nt], aL[mt].x, aH[mt].x, aL[mt].y, aH[mt].y, bf.x, bf.y);
                    mma16(acc2[mt][nt], aL[mt].z, aH[mt].z, aL[mt].w, aH[mt].w, bf.z, bf.w);
                }
            }
        }
    }

    // ================= epilogue: b2 + exact LayerNorm + scatter =================
    {
        const float* b2g = b2 + br * DH;
        #pragma unroll
        for (int nt = 0; nt < 4; nt++) {
            int col0 = wn * 32 + nt * 8 + 2 * tig;
            float2 bb = *(const float2*)(b2g + col0);
            #pragma unroll
            for (int mt = 0; mt < 2; mt++) {
                acc2[mt][nt][0] += bb.x; acc2[mt][nt][1] += bb.y;
                acc2[mt][nt][2] += bb.x; acc2[mt][nt][3] += bb.y;
            }
        }
        __syncthreads();
        float mu[4], rstd[4];
        #pragma unroll
        for (int rr = 0; rr < 4; rr++) {
            int mt = rr >> 1, hi = rr & 1;
            float sfull = 0.f;
            #pragma unroll
            for (int nt = 0; nt < 4; nt++) sfull += acc2[mt][nt][hi * 2] + acc2[mt][nt][hi * 2 + 1];
            sfull += __shfl_xor_sync(0xffffffffu, sfull, 1);
            sfull += __shfl_xor_sync(0xffffffffu, sfull, 2);
            int row = wm * 32 + mt * 16 + hi * 8 + g;
            if (tig == 0) red[row * 8 + wn] = sfull;
        }
        __syncthreads();
        #pragma unroll
        for (int rr = 0; rr < 4; rr++) {
            int mt = rr >> 1, hi = rr & 1;
            int row = wm * 32 + mt * 16 + hi * 8 + g;
            float s = 0.f;
            #pragma unroll
            for (int w = 0; w < 8; w++) s += red[row * 8 + w];
            mu[rr] = s * (1.f / 256.f);
        }
        __syncthreads();
        #pragma unroll
        for (int rr = 0; rr < 4; rr++) {
            int mt = rr >> 1, hi = rr & 1;
            float sq = 0.f;
            #pragma unroll
            for (int nt = 0; nt < 4; nt++) {
                float d0 = acc2[mt][nt][hi * 2] - mu[rr];
                float d1 = acc2[mt][nt][hi * 2 + 1] - mu[rr];
                sq += d0 * d0 + d1 * d1;
            }
            sq += __shfl_xor_sync(0xffffffffu, sq, 1);
            sq += __shfl_xor_sync(0xffffffffu, sq, 2);
            int row = wm * 32 + mt * 16 + hi * 8 + g;
            if (tig == 0) red[row * 8 + wn] = sq;
        }
        __syncthreads();
        #pragma unroll
        for (int rr = 0; rr < 4; rr++) {
            int mt = rr >> 1, hi = rr & 1;
            int row = wm * 32 + mt * 16 + hi * 8 + g;
            float s = 0.f;
            #pragma unroll
            for (int w = 0; w < 8; w++) s += red[row * 8 + w];
            rstd[rr] = rsqrtf(s * (1.f / 256.f) + 1e-12f);
        }

        const float* gg = gamma + br * DH;
        const float* be = beta + br * DH;
        #pragma unroll
        for (int rr = 0; rr < 4; rr++) {
            int mt = rr >> 1, hi = rr & 1;
            int row = wm * 32 + mt * 16 + hi * 8 + g;
            if (t0 + row < count) {
                float* o = out + (size_t)s_tok[row] * DH;
                #pragma unroll
                for (int nt = 0; nt < 4; nt++) {
                    int col0 = wn * 32 + nt * 8 + 2 * tig;
                    float2 gm = *(const float2*)(gg + col0);
                    float2 bt = *(const float2*)(be + col0);
                    float2 v;
                    v.x = (acc2[mt][nt][hi * 2] - mu[rr]) * rstd[rr] * gm.x + bt.x;
                    v.y = (acc2[mt][nt][hi * 2 + 1] - mu[rr]) * rstd[rr] * gm.y + bt.y;
                    *(float2*)(o + col0) = v;
                }
            }
        }
    }
}

extern "C" void kernel_launch(void* const* d_in, const int* in_sizes, int n_in,
                              void* d_out, int out_size) {
    const float* x     = (const float*)d_in[0];
    const int*   b_seq = (const int*)d_in[1];
    const float* w1    = (const float*)d_in[2];
    const float* b1    = (const float*)d_in[3];
    const float* w2    = (const float*)d_in[4];
    const float* b2    = (const float*)d_in[5];
    const float* gamma = (const float*)d_in[6];
    const float* beta  = (const float*)d_in[7];
    float* out = (float*)d_out;

    const int smem_bytes = SMEM_U32 * 4;
    cudaFuncSetAttribute(ffn_mma_kernel, cudaFuncAttributeMaxDynamicSharedMemorySize, smem_bytes);

    reset_counts_kernel<<<1, 32>>>();
    bucket_kernel<<<NTOK / 256, 256>>>(b_seq);
    prep_w_kernel<<<2048, 256>>>(w1, w2);
    zero_kernel<<<(NTOK * 64) / 256, 256>>>(b_seq, (float4*)out);
    ffn_mma_kernel<<<dim3(NTOK / TM, NB), THREADS, smem_bytes>>>(x, b1, b2, gamma, beta, out);
}

// round 17
// speedup vs baseline: 1.1150x; 1.1150x over previous
#include <cuda_runtime.h>
#include <cuda_fp16.h>
#include <math.h>
#include <stdint.h>

#define NTOK 65536
#define DH 256
#define DF 1024
#define NB 4
#define TM 64
#define THREADS 512

#define XS_STRIDE 144   // u32 units; ≡16 (mod 32): conflict-free uint4 LDS phases
#define HS_STRIDE 80
#define HS_BUF (64 * HS_STRIDE)

// smem offsets in u32 units
#define OFF_TOK 0
#define OFF_RED 64                 // 64 rows x 8 warp-partials
#define OFF_XS 576
#define OFF_HS (OFF_XS + 64 * XS_STRIDE)
#define SMEM_U32 (OFF_HS + 2 * HS_BUF)

__device__ int g_counts[NB + 1];        // [4] = zero-branch token count
__device__ int g_zero_next;             // chunk claim counter for idle-block zeroing
__device__ int g_idx[(NB + 1) * NTOK];  // bucket 4 = zero-branch tokens
// fp16 weights in m16n8k16 fragment-permuted layout.
// Each (fc, step, f/h) cell holds 32 fp16 = 4 uint4.
__device__ uint4 g_w1h[NB * 8 * 8 * 128 * 4];   // [br][fc8][step8][f128][4 uint4]
__device__ uint4 g_w2h[NB * 8 * 4 * 256 * 4];   // [br][fc8][step4][h256][4 uint4]

static __device__ __forceinline__ void mma16(float* c,
    uint32_t a0, uint32_t a1, uint32_t a2, uint32_t a3, uint32_t b0, uint32_t b1) {
    asm volatile("mma.sync.aligned.m16n8k16.row.col.f32.f16.f16.f32 "
                 "{%0,%1,%2,%3}, {%4,%5,%6,%7}, {%8,%9}, {%0,%1,%2,%3};"
                 : "+f"(c[0]), "+f"(c[1]), "+f"(c[2]), "+f"(c[3])
                 : "r"(a0), "r"(a1), "r"(a2), "r"(a3), "r"(b0), "r"(b1));
}

// fast ELU: abs error ~5e-7 near 0 (<< fp16 rounding of H)
static __device__ __forceinline__ float elu_fast(float v) {
    return v > 0.f ? v : (__expf(v) - 1.f);
}

// permutation within a 32-k block: element position for k
// t=(k&7)>>1, grp=(k>>4)&1, hi=(k>>3)&1, odd=k&1 -> p = t*8 + grp*4 + hi*2 + odd
static __device__ __forceinline__ int perm32(int kk) {
    return ((kk & 7) >> 1) * 8 + ((kk >> 4) & 1) * 4 + ((kk >> 3) & 1) * 2 + (kk & 1);
}

__global__ void reset_counts_kernel() {
    if (threadIdx.x < NB + 1) g_counts[threadIdx.x] = 0;
    if (threadIdx.x == 8) g_zero_next = 0;
}
__global__ void bucket_kernel(const int* __restrict__ b_seq) {
    int i = blockIdx.x * blockDim.x + threadIdx.x;
    int b = b_seq[i];
    int bucket = (b > 0) ? (b - 1) : NB;
    int pos = atomicAdd(&g_counts[bucket], 1);
    g_idx[bucket * NTOK + pos] = i;
}

// merged weight prep: blocks [0,1024) do w1, [1024,2048) do w2
__global__ void prep_w_kernel(const float* __restrict__ w1, const float* __restrict__ w2) {
    int bid = blockIdx.x;
    if (bid < 1024) {
        int t = bid * blockDim.x + threadIdx.x;
        int e = t * 4;
        int br = e >> 18;
        int rem = e & 262143;
        int f = rem >> 8;
        int k = rem & 255;
        float4 v = *(const float4*)(w1 + e);
        int fc = f >> 7, fl = f & 127, step = k >> 5, kk = k & 31;   // kk % 4 == 0
        int p = perm32(kk);                                           // even
        __half2* dst = (__half2*)g_w1h + (((((br * 8 + fc) * 8 + step) * 128 + fl) * 32) + p) / 2;
        dst[0] = __floats2half2_rn(v.x, v.y);
        dst[4] = __floats2half2_rn(v.z, v.w);   // k+2,k+3 -> p+8
    } else {
        int t = (bid - 1024) * blockDim.x + threadIdx.x;
        int e = t * 4;
        int br = e >> 18;
        int rem = e & 262143;
        int h = rem >> 10;
        int f = rem & 1023;
        float4 v = *(const float4*)(w2 + e);
        int fc = f >> 7, fl = f & 127, step = fl >> 5, kk = fl & 31;  // kk % 4 == 0
        int p = perm32(kk);
        __half2* dst = (__half2*)g_w2h + (((((br * 8 + fc) * 4 + step) * 256 + h) * 32) + p) / 2;
        dst[0] = __floats2half2_rn(v.x, v.y);
        dst[4] = __floats2half2_rn(v.z, v.w);
    }
}

__global__ __launch_bounds__(THREADS, 1)
void ffn_mma_kernel(const float* __restrict__ x,
                    const float* __restrict__ b1, const float* __restrict__ b2,
                    const float* __restrict__ gamma, const float* __restrict__ beta,
                    float* __restrict__ out)
{
    const int br = blockIdx.y;
    const int count = g_counts[br];
    const int t0 = blockIdx.x * TM;

    extern __shared__ uint32_t smem[];
    const int tid = threadIdx.x;

    if (t0 >= count) {
        // ---- idle block: zero-branch output zeroing (overlapped with heavy CTAs) ----
        const int c0 = g_counts[NB];
        const int nChunks = (c0 + 15) >> 4;   // 16 tokens per chunk
        const float4 z4 = make_float4(0.f, 0.f, 0.f, 0.f);
        for (;;) {
            if (tid == 0) smem[0] = (uint32_t)atomicAdd(&g_zero_next, 1);
            __syncthreads();
            int c = (int)smem[0];
            __syncthreads();
            if (c >= nChunks) return;
            int ti = c * 16 + (tid >> 5);     // 16 tokens, one warp each
            if (ti < c0) {
                int tok = g_idx[NB * NTOK + ti];
                float4* o = (float4*)(out + (size_t)tok * DH) + (tid & 31);
                o[0] = z4;
                o[32] = z4;
            }
        }
    }

    int* s_tok = (int*)(smem + OFF_TOK);
    float* red = (float*)(smem + OFF_RED);
    uint32_t* Xs = smem + OFF_XS;

    const int wid = tid >> 5, lane = tid & 31;
    const int g = lane >> 2, tig = lane & 3;
    const int wm = wid & 1, wn = wid >> 1;   // 2 m-warps x 8 n-warps

    if (tid < TM) {
        int r = t0 + tid;
        s_tok[tid] = g_idx[br * NTOK + (r < count ? r : count - 1)];
    }
    __syncthreads();

    // ---- stage X tile (once), fp16 + k-permuted: 8 threads/row, one 32-k block each ----
    {
        int row = tid >> 3, q = tid & 7;
        const float4* src = (const float4*)(x + (size_t)s_tok[row] * DH) + q * 8;
        uint32_t* xr = Xs + row * XS_STRIDE + q * 16;
        #pragma unroll
        for (int j = 0; j < 8; j++) {
            float4 d = src[j];
            int p = perm32(j * 4);
            __half2 h01 = __floats2half2_rn(d.x, d.y);
            __half2 h23 = __floats2half2_rn(d.z, d.w);
            uint32_t* dst = xr + (p >> 1);
            dst[0] = *(uint32_t*)&h01;
            dst[4] = *(uint32_t*)&h23;
        }
    }

    // lane-constant uint4 stream bases into the permuted weight arrays.
    // B-fragment streams are LINEAR across fc:
    //   GEMM1: w1s + t1*512,  t1 = fc*8 + s,  t1 in [0,64)
    //   GEMM2: w2s + t2*1024, t2 = fc*4 + s,  t2 in [0,32)
    const int c1base = ((wn * 16 + g) << 2) + tig;
    const int c2base = ((wn * 32 + g) << 2) + tig;
    const uint4* w1s = g_w1h + (size_t)br * 8 * 4096 + c1base;
    const uint4* w2s = g_w2h + (size_t)br * 8 * 4096 + c2base;

    float acc2[2][4][4];
    #pragma unroll
    for (int a = 0; a < 2; a++)
        #pragma unroll
        for (int bq = 0; bq < 4; bq++)
            #pragma unroll
            for (int cq = 0; cq < 4; cq++) acc2[a][bq][cq] = 0.f;

    // seed GEMM1 ring (t1 = 0), prefetch distance 1 (R14 config — reg-budget safe)
    uint4 bb1[2][2];
    #pragma unroll
    for (int nt = 0; nt < 2; nt++) bb1[0][nt] = __ldg(w1s + nt * 32);
    uint4 bb2[2][4];

    __syncthreads();

    #pragma unroll 1
    for (int fc = 0; fc < 8; fc++) {
        uint32_t* Hs = smem + OFF_HS + (fc & 1) * HS_BUF;

        // ========== GEMM1: C1[64x128] = X * W1chunk^T, 8 steps of k=32 ==========
        float c1[2][2][4];
        #pragma unroll
        for (int a = 0; a < 2; a++)
            #pragma unroll
            for (int bq = 0; bq < 2; bq++)
                #pragma unroll
                for (int cq = 0; cq < 4; cq++) c1[a][bq][cq] = 0.f;

        #pragma unroll
        for (int s = 0; s < 8; s++) {
            int t1 = fc * 8 + s;
            if (t1 + 1 < 64) {      // continuous cross-fc prefetch, slot (s+1)&1
                const uint4* p = w1s + (t1 + 1) * 512;
                #pragma unroll
                for (int nt = 0; nt < 2; nt++)
                    bb1[(s + 1) & 1][nt] = __ldg(p + nt * 32);
            }
            int cb = s * 16 + 4 * tig;
            uint4 aL[2], aH[2];
            #pragma unroll
            for (int mt = 0; mt < 2; mt++) {
                int r0 = wm * 32 + mt * 16 + g;
                aL[mt] = *(const uint4*)(Xs + r0 * XS_STRIDE + cb);
                aH[mt] = *(const uint4*)(Xs + (r0 + 8) * XS_STRIDE + cb);
            }
            #pragma unroll
            for (int mt = 0; mt < 2; mt++)
                #pragma unroll
                for (int nt = 0; nt < 2; nt++) {
                    const uint4 bf = bb1[s & 1][nt];
                    mma16(c1[mt][nt], aL[mt].x, aH[mt].x, aL[mt].y, aH[mt].y, bf.x, bf.y);
                    mma16(c1[mt][nt], aL[mt].z, aH[mt].z, aL[mt].w, aH[mt].w, bf.z, bf.w);
                }
        }

        // ========== bias + fast ELU -> Hs[fc&1] (fp16, permuted) ==========
        {
            const float* b1g = b1 + br * DF + fc * 128;
            #pragma unroll
            for (int nt = 0; nt < 2; nt++) {
                int col0 = wn * 16 + nt * 8 + 2 * tig;
                float ba = b1g[col0], bb = b1g[col0 + 1];
                int block = col0 >> 5;
                int p = perm32(col0 & 31);          // even
                int uoff = block * 16 + (p >> 1);
                #pragma unroll
                for (int mt = 0; mt < 2; mt++) {
                    int r0 = wm * 32 + mt * 16 + g;
                    float v00 = elu_fast(c1[mt][nt][0] + ba);
                    float v01 = elu_fast(c1[mt][nt][1] + bb);
                    float v10 = elu_fast(c1[mt][nt][2] + ba);
                    float v11 = elu_fast(c1[mt][nt][3] + bb);
                    __half2 hlo = __floats2half2_rn(v00, v01);
                    __half2 hhi = __floats2half2_rn(v10, v11);
                    Hs[r0 * HS_STRIDE + uoff] = *(uint32_t*)&hlo;
                    Hs[(r0 + 8) * HS_STRIDE + uoff] = *(uint32_t*)&hhi;
                }
            }
        }
        if (fc == 0) {    // seed GEMM2 ring before the barrier so the barrier hides L2
            #pragma unroll
            for (int nt = 0; nt < 4; nt++) bb2[0][nt] = __ldg(w2s + nt * 32);
        }
        __syncthreads();   // single barrier per fc: Hs[fc&1] writes -> reads.

        // ========== GEMM2: acc2[64x256] += H * W2chunk^T, 4 steps of k=32 ==========
        #pragma unroll
        for (int s = 0; s < 4; s++) {
            int t2 = fc * 4 + s;
            if (t2 + 1 < 32) {   // cross-fc prefetch: next fc's step0 lands during GEMM1+barrier
                const uint4* p = w2s + (t2 + 1) * 1024;
                #pragma unroll
                for (int nt = 0; nt < 4; nt++)
                    bb2[(s + 1) & 1][nt] = __ldg(p + nt * 32);
            }
            int cb = s * 16 + 4 * tig;
            uint4 aL[2], aH[2];
            #pragma unroll
            for (int mt = 0; mt < 2; mt++) {
                int r0 = wm * 32 + mt * 16 + g;
                aL[mt] = *(const uint4*)(Hs + r0 * HS_STRIDE + cb);
                aH[mt] = *(const uint4*)(Hs + (r0 + 8) * HS_STRIDE + cb);
            }
            #pragma unroll
            for (int nt = 0; nt < 4; nt++) {
                const uint4 bf = bb2[s & 1][nt];
                #pragma unroll
                for (int mt = 0; mt < 2; mt++) {
                    mma16(acc2[mt][nt], aL[mt].x, aH[mt].x, aL[mt].y, aH[mt].y, bf.x, bf.y);
                    mma16(acc2[mt][nt], aL[mt].z, aH[mt].z, aL[mt].w, aH[mt].w, bf.z, bf.w);
                }
            }
        }
    }

    // ================= epilogue: b2 + exact LayerNorm + scatter =================
    {
        const float* b2g = b2 + br * DH;
        #pragma unroll
        for (int nt = 0; nt < 4; nt++) {
            int col0 = wn * 32 + nt * 8 + 2 * tig;
            float2 bb = *(const float2*)(b2g + col0);
            #pragma unroll
            for (int mt = 0; mt < 2; mt++) {
                acc2[mt][nt][0] += bb.x; acc2[mt][nt][1] += bb.y;
                acc2[mt][nt][2] += bb.x; acc2[mt][nt][3] += bb.y;
            }
        }
        __syncthreads();
        float mu[4], rstd[4];
        #pragma unroll
        for (int rr = 0; rr < 4; rr++) {
            int mt = rr >> 1, hi = rr & 1;
            float sfull = 0.f;
            #pragma unroll
            for (int nt = 0; nt < 4; nt++) sfull += acc2[mt][nt][hi * 2] + acc2[mt][nt][hi * 2 + 1];
            sfull += __shfl_xor_sync(0xffffffffu, sfull, 1);
            sfull += __shfl_xor_sync(0xffffffffu, sfull, 2);
            int row = wm * 32 + mt * 16 + hi * 8 + g;
            if (tig == 0) red[row * 8 + wn] = sfull;
        }
        __syncthreads();
        #pragma unroll
        for (int rr = 0; rr < 4; rr++) {
            int mt = rr >> 1, hi = rr & 1;
            int row = wm * 32 + mt * 16 + hi * 8 + g;
            float s = 0.f;
            #pragma unroll
            for (int w = 0; w < 8; w++) s += red[row * 8 + w];
            mu[rr] = s * (1.f / 256.f);
        }
        __syncthreads();
        #pragma unroll
        for (int rr = 0; rr < 4; rr++) {
            int mt = rr >> 1, hi = rr & 1;
            float sq = 0.f;
            #pragma unroll
            for (int nt = 0; nt < 4; nt++) {
                float d0 = acc2[mt][nt][hi * 2] - mu[rr];
                float d1 = acc2[mt][nt][hi * 2 + 1] - mu[rr];
                sq += d0 * d0 + d1 * d1;
            }
            sq += __shfl_xor_sync(0xffffffffu, sq, 1);
            sq += __shfl_xor_sync(0xffffffffu, sq, 2);
            int row = wm * 32 + mt * 16 + hi * 8 + g;
            if (tig == 0) red[row * 8 + wn] = sq;
        }
        __syncthreads();
        #pragma unroll
        for (int rr = 0; rr < 4; rr++) {
            int mt = rr >> 1, hi = rr & 1;
            int row = wm * 32 + mt * 16 + hi * 8 + g;
            float s = 0.f;
            #pragma unroll
            for (int w = 0; w < 8; w++) s += red[row * 8 + w];
            rstd[rr] = rsqrtf(s * (1.f / 256.f) + 1e-12f);
        }

        const float* gg = gamma + br * DH;
        const float* be = beta + br * DH;
        #pragma unroll
        for (int rr = 0; rr < 4; rr++) {
            int mt = rr >> 1, hi = rr & 1;
            int row = wm * 32 + mt * 16 + hi * 8 + g;
            if (t0 + row < count) {
                float* o = out + (size_t)s_tok[row] * DH;
                #pragma unroll
                for (int nt = 0; nt < 4; nt++) {
                    int col0 = wn * 32 + nt * 8 + 2 * tig;
                    float2 gm = *(const float2*)(gg + col0);
                    float2 bt = *(const float2*)(be + col0);
                    float2 v;
                    v.x = (acc2[mt][nt][hi * 2] - mu[rr]) * rstd[rr] * gm.x + bt.x;
                    v.y = (acc2[mt][nt][hi * 2 + 1] - mu[rr]) * rstd[rr] * gm.y + bt.y;
                    *(float2*)(o + col0) = v;
                }
            }
        }
    }
}

extern "C" void kernel_launch(void* const* d_in, const int* in_sizes, int n_in,
                              void* d_out, int out_size) {
    const float* x     = (const float*)d_in[0];
    const int*   b_seq = (const int*)d_in[1];
    const float* w1    = (const float*)d_in[2];
    const float* b1    = (const float*)d_in[3];
    const float* w2    = (const float*)d_in[4];
    const float* b2    = (const float*)d_in[5];
    const float* gamma = (const float*)d_in[6];
    const float* beta  = (const float*)d_in[7];
    float* out = (float*)d_out;

    const int smem_bytes = SMEM_U32 * 4;
    cudaFuncSetAttribute(ffn_mma_kernel, cudaFuncAttributeMaxDynamicSharedMemorySize, smem_bytes);

    reset_counts_kernel<<<1, 32>>>();
    bucket_kernel<<<NTOK / 256, 256>>>(b_seq);
    prep_w_kernel<<<2048, 256>>>(w1, w2);
    ffn_mma_kernel<<<dim3(NTOK / TM, NB), THREADS, smem_bytes>>>(x, b1, b2, gamma, beta, out);
}